// round 8
// baseline (speedup 1.0000x reference)
#include <cuda_runtime.h>

#define Lg 2048
#define LMASK 2047
#define LSHIFT 11
#define NCELL (Lg * Lg)

#define R_OVER_5 0.5554f      /* 2.777 / 5 */
#define ETA 0.8f
#define ONE_MINUS_ETA 0.2f
#define GAMMA 0.8f
#define INV_K 2.0f            /* 1 / 0.5 */

// Tile geometry: 64 wide x 16 tall, 256 threads, 4 consecutive cells/thread
#define TX 64
#define TY 16
// type staging: rows row0-3 .. row0+18 (22), cols col0-4 .. col0+71 (76 = 19 int4)
#define TROWS 22
#define TV4   19               /* int4 per staged row */
#define TSTR4 20               /* padded stride in int4 */
#define TSTR  80               /* padded stride in ints */
// upd: rows row0-1 .. row0+16 (18), cols col0-1 .. col0+64 (66)
#define UROWS 18
#define UCOLS 66
#define USTR  68
#define NHALO 164              /* ring cells */

__global__ __launch_bounds__(256) void spgg_fused(
    const int* __restrict__ type_tm,
    const int* __restrict__ type_t,
    const float4* __restrict__ Q,
    const int* __restrict__ ldir,
    const float* __restrict__ lprob,
    float4* __restrict__ Q_out,
    float* __restrict__ type_out,
    float* __restrict__ profit_out)
{
    __shared__ int4  s_type4[TROWS * TSTR4];
    __shared__ float s_upd  [UROWS * USTR];
    const int* s_type = (const int*)s_type4;

    int tid  = threadIdx.x;
    int bx   = blockIdx.x & 31;    // 32 column tiles
    int by   = blockIdx.x >> 5;    // 128 row tiles
    int row0 = by * TY;
    int col0 = bx * TX;

    int tr = tid >> 4;             // 0..15 (row within tile)
    int c0 = (tid & 15) << 2;      // 0,4,..,60 (first of 4 consecutive cols)
    int gbase = ((row0 + tr) << LSHIFT) | (col0 + c0);

    // ---- Issue phase-1 staging loads (int4, wrap-indexed) ----
    int4 stage[2];
    int  sidx[2];
    #pragma unroll
    for (int k = 0; k < 2; k++) {
        int idx = tid + k * 256;
        if (idx < TROWS * TV4) {
            int r  = idx / TV4;
            int c4 = idx - r * TV4;
            int gr = (row0 - 3 + r) & LMASK;
            int gc = (col0 - 4 + (c4 << 2)) & LMASK;
            stage[k] = __ldg((const int4*)(type_t + (gr << LSHIFT) + gc));
            sidx[k]  = r * TSTR4 + c4;
        } else sidx[k] = -1;
    }

    // ---- Prefetch ALL per-cell streams at entry (no load after last sync) ----
    float4 qv[4];
    #pragma unroll
    for (int j = 0; j < 4; j++) qv[j] = __ldcs(Q + gbase + j);
    int4   av = __ldg ((const int4*)  (type_tm + gbase));
    int4   dv = __ldcs((const int4*)  (ldir    + gbase));
    float4 pv = __ldcs((const float4*)(lprob   + gbase));

    // ---- Prefetch halo-ring cell (threads 0..163) ----
    int hr = 0, hc = 0;
    float4 qh;
    int ah = 0;
    bool has_halo = (tid < NHALO);
    if (has_halo) {
        int h = tid;
        if (h < UCOLS)            { hr = 0;             hc = h;          }
        else if (h < 2 * UCOLS)   { hr = UROWS - 1;     hc = h - UCOLS;  }
        else { int s = h - 2 * UCOLS; hr = 1 + (s >> 1); hc = (s & 1) ? (UCOLS - 1) : 0; }
        int gr = (row0 - 1 + hr) & LMASK;
        int gc = (col0 - 1 + hc) & LMASK;
        int hg = (gr << LSHIFT) | gc;
        qh = __ldcs(Q + hg);
        ah = __ldg(type_tm + hg);
    }

    // ---- Complete staging, sync ----
    #pragma unroll
    for (int k = 0; k < 2; k++)
        if (sidx[k] >= 0) s_type4[sidx[k]] = stage[k];
    __syncthreads();

    // ---- Phase 2: profit (13-pt stencil from smem) + Q update ----
    int AV[4] = {av.x, av.y, av.z, av.w};
    float prf[4];
    #pragma unroll
    for (int j = 0; j < 4; j++) {
        int cc = c0 + j;
        const int* st = s_type + (tr + 3) * TSTR + (cc + 4);
        int t00  = st[0];
        int orth = st[-1] + st[1] + st[-TSTR] + st[TSTR];
        int diag = st[-TSTR - 1] + st[-TSTR + 1] + st[TSTR - 1] + st[TSTR + 1];
        int far2 = st[-2] + st[2] + st[-2 * TSTR] + st[2 * TSTR];
        int S2   = 5 * t00 + 2 * (orth + diag) + far2;
        float profit = (float)S2 * R_OVER_5 - 5.0f * (float)t00;

        float4 q = qv[j];
        int A = AV[j], B = t00;
        float maxv = B ? fmaxf(q.z, q.w) : fmaxf(q.x, q.y);
        float old  = B ? (A ? q.w : q.y) : (A ? q.z : q.x);
        float upd  = ONE_MINUS_ETA * old + ETA * (profit + GAMMA * maxv);
        if (A == 0) { if (B == 0) q.x = upd; else q.y = upd; }
        else        { if (B == 0) q.z = upd; else q.w = upd; }

        s_upd[(tr + 1) * USTR + (cc + 1)] = upd;
        prf[j] = profit;
        __stcs(Q_out + gbase + j, q);
    }
    __stcs((float4*)(profit_out + gbase), make_float4(prf[0], prf[1], prf[2], prf[3]));

    // halo cells: upd coords (hr, hc) -> type coords (hr+2, hc+3)
    if (has_halo) {
        const int* st = s_type + (hr + 2) * TSTR + (hc + 3);
        int t00  = st[0];
        int orth = st[-1] + st[1] + st[-TSTR] + st[TSTR];
        int diag = st[-TSTR - 1] + st[-TSTR + 1] + st[TSTR - 1] + st[TSTR + 1];
        int far2 = st[-2] + st[2] + st[-2 * TSTR] + st[2 * TSTR];
        int S2   = 5 * t00 + 2 * (orth + diag) + far2;
        float profit = (float)S2 * R_OVER_5 - 5.0f * (float)t00;

        float4 q = qh;
        int A = ah, B = t00;
        float maxv = B ? fmaxf(q.z, q.w) : fmaxf(q.x, q.y);
        float old  = B ? (A ? q.w : q.y) : (A ? q.z : q.x);
        s_upd[hr * USTR + hc] = ONE_MINUS_ETA * old + ETA * (profit + GAMMA * maxv);
    }
    __syncthreads();

    // ---- Phase 3: fermi entirely from smem + prefetched dirs/probs ----
    int DV[4] = {dv.x, dv.y, dv.z, dv.w};
    float PV[4] = {pv.x, pv.y, pv.z, pv.w};
    float ov[4];
    #pragma unroll
    for (int j = 0; j < 4; j++) {
        int cc = c0 + j;
        float u = s_upd[(tr + 1) * USTR + (cc + 1)];

        int d = DV[j];
        int ur, uc;
        if (d == 0)      { ur = tr + 1; uc = cc;     }   // col-1
        else if (d == 1) { ur = tr + 1; uc = cc + 2; }   // col+1
        else if (d == 2) { ur = tr;     uc = cc + 1; }   // row-1
        else             { ur = tr + 2; uc = cc + 1; }   // row+1

        float un = s_upd[ur * USTR + uc];
        int tmine = s_type[(tr + 3) * TSTR + (cc + 4)];
        int tn    = s_type[(ur + 2) * TSTR + (uc + 3)];

        float W = 1.0f / (1.0f + __expf((u - un) * INV_K));
        ov[j] = (float)((PV[j] <= W) ? tn : tmine);
    }
    __stcs((float4*)(type_out + gbase), make_float4(ov[0], ov[1], ov[2], ov[3]));
}

// ---------------------------------------------------------------------------
// Launch: output layout = concat(Q_new[4N], type_t1[N], profit[N]) as float32
// ---------------------------------------------------------------------------
extern "C" void kernel_launch(void* const* d_in, const int* in_sizes, int n_in,
                              void* d_out, int out_size)
{
    const int*    type_tm = (const int*)   d_in[0];
    const int*    type_t  = (const int*)   d_in[1];
    const float4* Q       = (const float4*)d_in[2];
    const int*    ldir    = (const int*)   d_in[3];
    const float*  lprob   = (const float*) d_in[4];

    float* out        = (float*)d_out;
    float4* Q_out     = (float4*)out;                 // [0, 4N)
    float* type_out   = out + 4 * (size_t)NCELL;      // [4N, 5N)
    float* profit_out = out + 5 * (size_t)NCELL;      // [5N, 6N)

    const int blocks = (Lg / TX) * (Lg / TY);         // 4096

    spgg_fused<<<blocks, 256>>>(type_tm, type_t, Q, ldir, lprob,
                                Q_out, type_out, profit_out);
}

// round 9
// speedup vs baseline: 1.2137x; 1.2137x over previous
#include <cuda_runtime.h>

#define Lg 2048
#define LMASK 2047
#define LSHIFT 11
#define NCELL (Lg * Lg)

#define R_OVER_5 0.5554f      /* 2.777 / 5 */
#define ETA 0.8f
#define ONE_MINUS_ETA 0.2f
#define GAMMA 0.8f
#define INV_K 2.0f            /* 1 / 0.5 */

// Tile geometry: 64 wide x 16 tall, 256 threads, 4 inner cells/thread (col-major map)
#define TX 64
#define TY 16
// type staging: rows row0-3 .. row0+18 (22), cols col0-4 .. col0+71 (76 = 19 int4)
#define TROWS 22
#define TV4   19               /* int4 per staged row */
#define TSTR4 20               /* padded stride in int4 */
#define TSTR  80               /* padded stride in ints */
// upd: rows row0-1 .. row0+16 (18), cols col0-1 .. col0+64 (66)
#define UROWS 18
#define UCOLS 66
#define USTR  68
#define NHALO 164              /* ring cells */

__global__ __launch_bounds__(256) void spgg_fused(
    const int* __restrict__ type_tm,
    const int* __restrict__ type_t,
    const float4* __restrict__ Q,
    const int* __restrict__ ldir,
    const float* __restrict__ lprob,
    float4* __restrict__ Q_out,
    float* __restrict__ type_out,
    float* __restrict__ profit_out)
{
    __shared__ int4   s_type4[TROWS * TSTR4];
    __shared__ float  s_upd  [UROWS * USTR];
    __shared__ int4   s_dir4 [256];     // 16x64 dirs, int4-packed
    __shared__ float4 s_prob4[256];     // 16x64 probs
    const int* s_type = (const int*)s_type4;
    const int*   s_dir  = (const int*)s_dir4;
    const float* s_prob = (const float*)s_prob4;

    int tid  = threadIdx.x;
    int bx   = blockIdx.x & 31;    // 32 column tiles
    int by   = blockIdx.x >> 5;    // 128 row tiles
    int row0 = by * TY;
    int col0 = bx * TX;

    int tr0 = tid >> 6;            // 0..3
    int tc  = tid & 63;

    // ---- Stage ldir/lprob to smem (row-major coalesced, registers die here) ----
    {
        int r  = tid >> 4;
        int c4 = (tid & 15) << 2;
        int g  = ((row0 + r) << LSHIFT) | (col0 + c4);
        s_dir4 [tid] = __ldcs((const int4*)  (ldir  + g));
        s_prob4[tid] = __ldcs((const float4*)(lprob + g));
    }

    // ---- Issue phase-1 type staging loads (int4, wrap-indexed) ----
    int4 stage[2];
    int  sidx[2];
    #pragma unroll
    for (int k = 0; k < 2; k++) {
        int idx = tid + k * 256;
        if (idx < TROWS * TV4) {
            int r  = idx / TV4;
            int c4 = idx - r * TV4;
            int gr = (row0 - 3 + r) & LMASK;
            int gc = (col0 - 4 + (c4 << 2)) & LMASK;
            stage[k] = __ldg((const int4*)(type_t + (gr << LSHIFT) + gc));
            sidx[k]  = r * TSTR4 + c4;
        } else sidx[k] = -1;
    }

    // ---- Prefetch inner-cell Q/tm (4 cells per thread, col-major mapping) ----
    int gidx[4];
    float4 qv[4];
    int av[4];
    #pragma unroll
    for (int j = 0; j < 4; j++) {
        int tr = (tr0 << 2) + j;                  // 0..15
        gidx[j] = ((row0 + tr) << LSHIFT) | (col0 + tc);
        qv[j] = __ldcs(Q + gidx[j]);
        av[j] = __ldg(type_tm + gidx[j]);
    }

    // ---- Prefetch halo-ring cell (threads 0..163) ----
    int hr = 0, hc = 0;
    float4 qh;
    int ah = 0;
    bool has_halo = (tid < NHALO);
    if (has_halo) {
        int h = tid;
        if (h < UCOLS)            { hr = 0;             hc = h;          }
        else if (h < 2 * UCOLS)   { hr = UROWS - 1;     hc = h - UCOLS;  }
        else { int s = h - 2 * UCOLS; hr = 1 + (s >> 1); hc = (s & 1) ? (UCOLS - 1) : 0; }
        int gr = (row0 - 1 + hr) & LMASK;
        int gc = (col0 - 1 + hc) & LMASK;
        int hg = (gr << LSHIFT) | gc;
        qh = __ldcs(Q + hg);
        ah = __ldg(type_tm + hg);
    }

    // ---- Complete type staging, sync ----
    #pragma unroll
    for (int k = 0; k < 2; k++)
        if (sidx[k] >= 0) s_type4[sidx[k]] = stage[k];
    __syncthreads();

    // ---- Phase 2: profit (13-pt stencil from smem) + Q update ----
    #pragma unroll
    for (int j = 0; j < 4; j++) {
        int tr = (tr0 << 2) + j;
        const int* st = s_type + (tr + 3) * TSTR + (tc + 4);
        int t00  = st[0];
        int orth = st[-1] + st[1] + st[-TSTR] + st[TSTR];
        int diag = st[-TSTR - 1] + st[-TSTR + 1] + st[TSTR - 1] + st[TSTR + 1];
        int far2 = st[-2] + st[2] + st[-2 * TSTR] + st[2 * TSTR];
        int S2   = 5 * t00 + 2 * (orth + diag) + far2;
        float profit = (float)S2 * R_OVER_5 - 5.0f * (float)t00;

        float4 q = qv[j];
        int A = av[j], B = t00;
        float maxv = B ? fmaxf(q.z, q.w) : fmaxf(q.x, q.y);
        float old  = B ? (A ? q.w : q.y) : (A ? q.z : q.x);
        float upd  = ONE_MINUS_ETA * old + ETA * (profit + GAMMA * maxv);
        if (A == 0) { if (B == 0) q.x = upd; else q.y = upd; }
        else        { if (B == 0) q.z = upd; else q.w = upd; }

        s_upd[(tr + 1) * USTR + (tc + 1)] = upd;
        __stcs(Q_out + gidx[j], q);
        __stcs(profit_out + gidx[j], profit);
    }

    // halo cells: upd coords (hr, hc) -> type coords (hr+2, hc+3)
    if (has_halo) {
        const int* st = s_type + (hr + 2) * TSTR + (hc + 3);
        int t00  = st[0];
        int orth = st[-1] + st[1] + st[-TSTR] + st[TSTR];
        int diag = st[-TSTR - 1] + st[-TSTR + 1] + st[TSTR - 1] + st[TSTR + 1];
        int far2 = st[-2] + st[2] + st[-2 * TSTR] + st[2 * TSTR];
        int S2   = 5 * t00 + 2 * (orth + diag) + far2;
        float profit = (float)S2 * R_OVER_5 - 5.0f * (float)t00;

        float4 q = qh;
        int A = ah, B = t00;
        float maxv = B ? fmaxf(q.z, q.w) : fmaxf(q.x, q.y);
        float old  = B ? (A ? q.w : q.y) : (A ? q.z : q.x);
        s_upd[hr * USTR + hc] = ONE_MINUS_ETA * old + ETA * (profit + GAMMA * maxv);
    }
    __syncthreads();

    // ---- Phase 3: fermi entirely from smem (zero global loads) ----
    #pragma unroll
    for (int j = 0; j < 4; j++) {
        int tr = (tr0 << 2) + j;

        int   d = s_dir [tr * 64 + tc];
        float p = s_prob[tr * 64 + tc];

        float u = s_upd[(tr + 1) * USTR + (tc + 1)];

        int ur, uc;
        if (d == 0)      { ur = tr + 1; uc = tc;     }   // col-1
        else if (d == 1) { ur = tr + 1; uc = tc + 2; }   // col+1
        else if (d == 2) { ur = tr;     uc = tc + 1; }   // row-1
        else             { ur = tr + 2; uc = tc + 1; }   // row+1

        float un = s_upd[ur * USTR + uc];
        int tmine = s_type[(tr + 3) * TSTR + (tc + 4)];
        int tn    = s_type[(ur + 2) * TSTR + (uc + 3)];

        float W = 1.0f / (1.0f + __expf((u - un) * INV_K));
        int out = (p <= W) ? tn : tmine;
        __stcs(type_out + gidx[j], (float)out);
    }
}

// ---------------------------------------------------------------------------
// Launch: output layout = concat(Q_new[4N], type_t1[N], profit[N]) as float32
// ---------------------------------------------------------------------------
extern "C" void kernel_launch(void* const* d_in, const int* in_sizes, int n_in,
                              void* d_out, int out_size)
{
    const int*    type_tm = (const int*)   d_in[0];
    const int*    type_t  = (const int*)   d_in[1];
    const float4* Q       = (const float4*)d_in[2];
    const int*    ldir    = (const int*)   d_in[3];
    const float*  lprob   = (const float*) d_in[4];

    float* out        = (float*)d_out;
    float4* Q_out     = (float4*)out;                 // [0, 4N)
    float* type_out   = out + 4 * (size_t)NCELL;      // [4N, 5N)
    float* profit_out = out + 5 * (size_t)NCELL;      // [5N, 6N)

    const int blocks = (Lg / TX) * (Lg / TY);         // 4096

    spgg_fused<<<blocks, 256>>>(type_tm, type_t, Q, ldir, lprob,
                                Q_out, type_out, profit_out);
}